// round 1
// baseline (speedup 1.0000x reference)
#include <cuda_runtime.h>

#define B_ 4
#define N_ 1024
#define C_ 768
#define H_ 12
#define BN (B_*N_)          // 4096
#define SCALE 0.125f

// Scratch (static device globals — no allocations allowed)
__device__ float g_Q[(size_t)B_*H_*N_*128];   // [B,H,N,128] streams concat along D
__device__ float g_K[(size_t)B_*H_*N_*128];
__device__ float g_V[(size_t)B_*H_*N_*128];
__device__ float g_O[(size_t)2*BN*C_];        // o1 then o2, [B*N, C]

// ---------------------------------------------------------------------------
// Kernel 1: qkv = x @ W_qkv^T + b, scatter into Q/K/V [B,H,N,128] (stream*64+d)
// grid (2304/64, 4096/64, 2 streams), 256 threads, 64x64 tile, 4x4 micro
// ---------------------------------------------------------------------------
__global__ __launch_bounds__(256) void qkv_kernel(
    const float* __restrict__ x1, const float* __restrict__ x2,
    const float* __restrict__ W, const float* __restrict__ bias)
{
    __shared__ float As[16][68];
    __shared__ float Bs[16][68];
    const int stream = blockIdx.z;
    const float* __restrict__ X = stream ? x2 : x1;
    const int c0 = blockIdx.x * 64;
    const int m0 = blockIdx.y * 64;
    const int t  = threadIdx.x;
    const int ty = t >> 4, tx = t & 15;
    const int lm  = t >> 2;      // 0..63 tile row
    const int lk4 = t & 3;       // float4 index along k

    float acc[4][4];
#pragma unroll
    for (int i = 0; i < 4; i++)
#pragma unroll
        for (int j = 0; j < 4; j++) acc[i][j] = 0.f;

    const float* aptr = X + (size_t)(m0 + lm) * C_ + lk4 * 4;
    const float* bptr = W + (size_t)(c0 + lm) * C_ + lk4 * 4;

    for (int kk = 0; kk < C_; kk += 16) {
        float4 a = *(const float4*)(aptr + kk);
        float4 b = *(const float4*)(bptr + kk);
        As[lk4*4+0][lm] = a.x; As[lk4*4+1][lm] = a.y;
        As[lk4*4+2][lm] = a.z; As[lk4*4+3][lm] = a.w;
        Bs[lk4*4+0][lm] = b.x; Bs[lk4*4+1][lm] = b.y;
        Bs[lk4*4+2][lm] = b.z; Bs[lk4*4+3][lm] = b.w;
        __syncthreads();
#pragma unroll
        for (int k = 0; k < 16; k++) {
            float4 av = *(const float4*)&As[k][ty*4];
            float4 bv = *(const float4*)&Bs[k][tx*4];
            acc[0][0] += av.x*bv.x; acc[0][1] += av.x*bv.y; acc[0][2] += av.x*bv.z; acc[0][3] += av.x*bv.w;
            acc[1][0] += av.y*bv.x; acc[1][1] += av.y*bv.y; acc[1][2] += av.y*bv.z; acc[1][3] += av.y*bv.w;
            acc[2][0] += av.z*bv.x; acc[2][1] += av.z*bv.y; acc[2][2] += av.z*bv.z; acc[2][3] += av.z*bv.w;
            acc[3][0] += av.w*bv.x; acc[3][1] += av.w*bv.y; acc[3][2] += av.w*bv.z; acc[3][3] += av.w*bv.w;
        }
        __syncthreads();
    }

    // tile covers exactly one (s, h): c0 is a multiple of 64, C_=768 is 64-aligned
    const int s   = c0 / C_;
    const int rem = c0 - s * C_;
    const int h   = rem >> 6;
    float* __restrict__ buf = (s == 0) ? g_Q : (s == 1) ? g_K : g_V;
    float4 bb = *(const float4*)&bias[c0 + tx*4];

#pragma unroll
    for (int i = 0; i < 4; i++) {
        int m = m0 + ty*4 + i;
        int b = m >> 10, n = m & 1023;
        float4 v;
        v.x = acc[i][0] + bb.x;
        v.y = acc[i][1] + bb.y;
        v.z = acc[i][2] + bb.z;
        v.w = acc[i][3] + bb.w;
        *(float4*)&buf[((size_t)(b*H_ + h) * N_ + n) * 128 + stream*64 + tx*4] = v;
    }
}

// ---------------------------------------------------------------------------
// Kernel 2: flash attention, head-dim 128 (dual stream concat), 64-row Q tiles
// grid (N/64, B*H), 256 threads. Dynamic smem ~121.6 KB.
// ---------------------------------------------------------------------------
__global__ __launch_bounds__(256) void attn_kernel()
{
    extern __shared__ float sm[];
    float* Qt  = sm;                  // [128][68]  Q transposed (pre-scaled)
    float* Kt  = Qt + 128*68;         // [128][68]  K transposed
    float* Vs  = Kt + 128*68;         // [64][132]  V natural
    float* Ps  = Vs + 64*132;         // [64][68]   scores / probs
    float* m_s = Ps + 64*68;          // [64]
    float* l_s = m_s + 64;            // [64]
    float* f_s = l_s + 64;            // [64]

    const int bh = blockIdx.y;
    const int qt = blockIdx.x;
    const int t  = threadIdx.x;
    const int ry = t >> 4;            // 0..15 (row group: rows ry*4..+3)
    const int cx = t & 15;            // 0..15 (cols cx*4..+3 and 64+cx*4..+3)

    const float* __restrict__ Qg = g_Q + (size_t)bh * N_ * 128 + (size_t)qt * 64 * 128;
    const float* __restrict__ Kg = g_K + (size_t)bh * N_ * 128;
    const float* __restrict__ Vg = g_V + (size_t)bh * N_ * 128;

    // load Q tile transposed, apply softmax scale once
#pragma unroll
    for (int it = 0; it < 8; it++) {
        int idx = t + it*256;
        int r = idx >> 5, d4 = idx & 31;
        float4 v = *(const float4*)&Qg[r*128 + d4*4];
        Qt[(d4*4+0)*68 + r] = v.x * SCALE;
        Qt[(d4*4+1)*68 + r] = v.y * SCALE;
        Qt[(d4*4+2)*68 + r] = v.z * SCALE;
        Qt[(d4*4+3)*68 + r] = v.w * SCALE;
    }
    if (t < 64) { m_s[t] = -1e30f; l_s[t] = 0.f; }

    float o[32];
#pragma unroll
    for (int i = 0; i < 32; i++) o[i] = 0.f;

    for (int kt = 0; kt < 16; kt++) {
        __syncthreads();   // previous PV done (and Q visible on first iter)
#pragma unroll
        for (int it = 0; it < 8; it++) {
            int idx = t + it*256;
            int r = idx >> 5, d4 = idx & 31;
            float4 kv = *(const float4*)&Kg[(kt*64 + r)*128 + d4*4];
            Kt[(d4*4+0)*68 + r] = kv.x;
            Kt[(d4*4+1)*68 + r] = kv.y;
            Kt[(d4*4+2)*68 + r] = kv.z;
            Kt[(d4*4+3)*68 + r] = kv.w;
            float4 vv = *(const float4*)&Vg[(kt*64 + r)*128 + d4*4];
            *(float4*)&Vs[r*132 + d4*4] = vv;
        }
        __syncthreads();

        // S[r][c] = sum_k Qt[k][r] * Kt[k][c]   (64x64, K=128)
        float s4[4][4];
#pragma unroll
        for (int i = 0; i < 4; i++)
#pragma unroll
            for (int j = 0; j < 4; j++) s4[i][j] = 0.f;
#pragma unroll 4
        for (int k = 0; k < 128; k++) {
            float4 qv = *(const float4*)&Qt[k*68 + ry*4];
            float4 kv = *(const float4*)&Kt[k*68 + cx*4];
            s4[0][0] += qv.x*kv.x; s4[0][1] += qv.x*kv.y; s4[0][2] += qv.x*kv.z; s4[0][3] += qv.x*kv.w;
            s4[1][0] += qv.y*kv.x; s4[1][1] += qv.y*kv.y; s4[1][2] += qv.y*kv.z; s4[1][3] += qv.y*kv.w;
            s4[2][0] += qv.z*kv.x; s4[2][1] += qv.z*kv.y; s4[2][2] += qv.z*kv.z; s4[2][3] += qv.z*kv.w;
            s4[3][0] += qv.w*kv.x; s4[3][1] += qv.w*kv.y; s4[3][2] += qv.w*kv.z; s4[3][3] += qv.w*kv.w;
        }
#pragma unroll
        for (int i = 0; i < 4; i++)
            *(float4*)&Ps[(ry*4+i)*68 + cx*4] =
                make_float4(s4[i][0], s4[i][1], s4[i][2], s4[i][3]);
        __syncthreads();

        // online softmax: one thread per row
        if (t < 64) {
            float mold = m_s[t];
            float mloc = mold;
            float* prow = &Ps[t*68];
#pragma unroll 8
            for (int c = 0; c < 64; c++) mloc = fmaxf(mloc, prow[c]);
            float sum = 0.f;
#pragma unroll 8
            for (int c = 0; c < 64; c++) {
                float p = __expf(prow[c] - mloc);
                prow[c] = p;
                sum += p;
            }
            float fac = __expf(mold - mloc);
            l_s[t] = l_s[t]*fac + sum;
            m_s[t] = mloc;
            f_s[t] = fac;
        }
        __syncthreads();

        // rescale O, then O += P @ V
        float f0 = f_s[ry*4+0], f1 = f_s[ry*4+1], f2 = f_s[ry*4+2], f3 = f_s[ry*4+3];
#pragma unroll
        for (int j = 0; j < 8; j++) {
            o[0*8+j] *= f0; o[1*8+j] *= f1; o[2*8+j] *= f2; o[3*8+j] *= f3;
        }
#pragma unroll 2
        for (int j = 0; j < 64; j++) {
            float p0 = Ps[(ry*4+0)*68 + j];
            float p1 = Ps[(ry*4+1)*68 + j];
            float p2 = Ps[(ry*4+2)*68 + j];
            float p3 = Ps[(ry*4+3)*68 + j];
            float4 va = *(const float4*)&Vs[j*132 + cx*4];
            float4 vb = *(const float4*)&Vs[j*132 + 64 + cx*4];
            o[0]  += p0*va.x; o[1]  += p0*va.y; o[2]  += p0*va.z; o[3]  += p0*va.w;
            o[4]  += p0*vb.x; o[5]  += p0*vb.y; o[6]  += p0*vb.z; o[7]  += p0*vb.w;
            o[8]  += p1*va.x; o[9]  += p1*va.y; o[10] += p1*va.z; o[11] += p1*va.w;
            o[12] += p1*vb.x; o[13] += p1*vb.y; o[14] += p1*vb.z; o[15] += p1*vb.w;
            o[16] += p2*va.x; o[17] += p2*va.y; o[18] += p2*va.z; o[19] += p2*va.w;
            o[20] += p2*vb.x; o[21] += p2*vb.y; o[22] += p2*vb.z; o[23] += p2*vb.w;
            o[24] += p3*va.x; o[25] += p3*va.y; o[26] += p3*va.z; o[27] += p3*va.w;
            o[28] += p3*vb.x; o[29] += p3*vb.y; o[30] += p3*vb.z; o[31] += p3*vb.w;
        }
    }

    // epilogue: normalize and write both streams to [B*N, C] layout
    const int b = bh / H_, h = bh % H_;
    float* __restrict__ O1 = g_O;
    float* __restrict__ O2 = g_O + (size_t)BN * C_;
#pragma unroll
    for (int i = 0; i < 4; i++) {
        float linv = 1.f / l_s[ry*4+i];
        int n = qt*64 + ry*4 + i;
        size_t row = ((size_t)(b*N_ + n)) * C_ + h*64 + cx*4;
        float4 w1 = make_float4(o[i*8+0]*linv, o[i*8+1]*linv, o[i*8+2]*linv, o[i*8+3]*linv);
        float4 w2 = make_float4(o[i*8+4]*linv, o[i*8+5]*linv, o[i*8+6]*linv, o[i*8+7]*linv);
        *(float4*)&O1[row] = w1;
        *(float4*)&O2[row] = w2;
    }
}

// ---------------------------------------------------------------------------
// Kernel 3: y = O @ W_proj^T + b, both streams, written straight into d_out
// grid (768/64, 4096/64, 2), 256 threads
// ---------------------------------------------------------------------------
__global__ __launch_bounds__(256) void proj_kernel(
    const float* __restrict__ W, const float* __restrict__ bias,
    float* __restrict__ out)
{
    __shared__ float As[16][68];
    __shared__ float Bs[16][68];
    const int stream = blockIdx.z;
    const float* __restrict__ X = g_O + (size_t)stream * BN * C_;
    float* __restrict__ Y = out + (size_t)stream * BN * C_;
    const int c0 = blockIdx.x * 64;
    const int m0 = blockIdx.y * 64;
    const int t  = threadIdx.x;
    const int ty = t >> 4, tx = t & 15;
    const int lm  = t >> 2;
    const int lk4 = t & 3;

    float acc[4][4];
#pragma unroll
    for (int i = 0; i < 4; i++)
#pragma unroll
        for (int j = 0; j < 4; j++) acc[i][j] = 0.f;

    const float* aptr = X + (size_t)(m0 + lm) * C_ + lk4 * 4;
    const float* bptr = W + (size_t)(c0 + lm) * C_ + lk4 * 4;

    for (int kk = 0; kk < C_; kk += 16) {
        float4 a = *(const float4*)(aptr + kk);
        float4 b = *(const float4*)(bptr + kk);
        As[lk4*4+0][lm] = a.x; As[lk4*4+1][lm] = a.y;
        As[lk4*4+2][lm] = a.z; As[lk4*4+3][lm] = a.w;
        Bs[lk4*4+0][lm] = b.x; Bs[lk4*4+1][lm] = b.y;
        Bs[lk4*4+2][lm] = b.z; Bs[lk4*4+3][lm] = b.w;
        __syncthreads();
#pragma unroll
        for (int k = 0; k < 16; k++) {
            float4 av = *(const float4*)&As[k][ty*4];
            float4 bv = *(const float4*)&Bs[k][tx*4];
            acc[0][0] += av.x*bv.x; acc[0][1] += av.x*bv.y; acc[0][2] += av.x*bv.z; acc[0][3] += av.x*bv.w;
            acc[1][0] += av.y*bv.x; acc[1][1] += av.y*bv.y; acc[1][2] += av.y*bv.z; acc[1][3] += av.y*bv.w;
            acc[2][0] += av.z*bv.x; acc[2][1] += av.z*bv.y; acc[2][2] += av.z*bv.z; acc[2][3] += av.z*bv.w;
            acc[3][0] += av.w*bv.x; acc[3][1] += av.w*bv.y; acc[3][2] += av.w*bv.z; acc[3][3] += av.w*bv.w;
        }
        __syncthreads();
    }

    float4 bb = *(const float4*)&bias[c0 + tx*4];
#pragma unroll
    for (int i = 0; i < 4; i++) {
        int m = m0 + ty*4 + i;
        float4 v;
        v.x = acc[i][0] + bb.x;
        v.y = acc[i][1] + bb.y;
        v.z = acc[i][2] + bb.z;
        v.w = acc[i][3] + bb.w;
        *(float4*)&Y[(size_t)m * C_ + c0 + tx*4] = v;
    }
}

// ---------------------------------------------------------------------------
extern "C" void kernel_launch(void* const* d_in, const int* in_sizes, int n_in,
                              void* d_out, int out_size)
{
    (void)in_sizes; (void)n_in; (void)out_size;
    const float* x1    = (const float*)d_in[0];
    const float* x2    = (const float*)d_in[1];
    const float* Wqkv  = (const float*)d_in[2];
    const float* bqkv  = (const float*)d_in[3];
    const float* Wproj = (const float*)d_in[4];
    const float* bproj = (const float*)d_in[5];
    float* out = (float*)d_out;

    qkv_kernel<<<dim3(36, 64, 2), 256>>>(x1, x2, Wqkv, bqkv);

    const int smem_bytes = (128*68*2 + 64*132 + 64*68 + 192) * (int)sizeof(float); // 121,600 B
    cudaFuncSetAttribute(attn_kernel, cudaFuncAttributeMaxDynamicSharedMemorySize, smem_bytes);
    attn_kernel<<<dim3(16, 48), 256, smem_bytes>>>();

    proj_kernel<<<dim3(12, 64, 2), 256>>>(Wproj, bproj, out);
}

// round 3
// speedup vs baseline: 1.3189x; 1.3189x over previous
#include <cuda_runtime.h>
#include <cuda_bf16.h>
#include <cstdint>

#define B_ 4
#define N_ 1024
#define C_ 768
#define H_ 12
#define BN 4096
#define SCALE 0.125f

// ---------------- scratch (static device globals; no allocations) ----------
__device__ float g_Q[(size_t)B_*H_*N_*128];   // [B,H,N,128] streams concat on D
__device__ float g_K[(size_t)B_*H_*N_*128];
__device__ float g_V[(size_t)B_*H_*N_*128];
__device__ float g_O[(size_t)2*BN*C_];        // attention output, both streams

__device__ __align__(16) __nv_bfloat16 g_Xh[(size_t)2*BN*C_];
__device__ __align__(16) __nv_bfloat16 g_Xl[(size_t)2*BN*C_];
__device__ __align__(16) __nv_bfloat16 g_Wqh[(size_t)3*C_*C_];
__device__ __align__(16) __nv_bfloat16 g_Wql[(size_t)3*C_*C_];
__device__ __align__(16) __nv_bfloat16 g_Wph[(size_t)C_*C_];
__device__ __align__(16) __nv_bfloat16 g_Wpl[(size_t)C_*C_];
__device__ __align__(16) __nv_bfloat16 g_Oh[(size_t)2*BN*C_];
__device__ __align__(16) __nv_bfloat16 g_Ol[(size_t)2*BN*C_];

// ---------------- helpers ---------------------------------------------------
__device__ __forceinline__ uint32_t smem_u32(const void* p) {
    uint32_t a;
    asm("{ .reg .u64 t; cvta.to.shared.u64 t, %1; cvt.u32.u64 %0, t; }"
        : "=r"(a) : "l"(p));
    return a;
}

__device__ __forceinline__ uint32_t swz(uint32_t o) {   // SW128: bits[6:4] ^= bits[9:7]
    return o ^ ((o >> 3) & 0x70);
}

__device__ __forceinline__ void ldsm_x4(uint32_t* r, uint32_t addr) {
    asm volatile("ldmatrix.sync.aligned.m8n8.x4.shared.b16 {%0,%1,%2,%3}, [%4];"
                 : "=r"(r[0]), "=r"(r[1]), "=r"(r[2]), "=r"(r[3]) : "r"(addr));
}
__device__ __forceinline__ void ldsm_x2(uint32_t* r, uint32_t addr) {
    asm volatile("ldmatrix.sync.aligned.m8n8.x2.shared.b16 {%0,%1}, [%2];"
                 : "=r"(r[0]), "=r"(r[1]) : "r"(addr));
}
__device__ __forceinline__ void mma16816(float* d, const uint32_t* a, const uint32_t* b) {
    asm volatile(
        "mma.sync.aligned.m16n8k16.row.col.f32.bf16.bf16.f32 "
        "{%0,%1,%2,%3}, {%4,%5,%6,%7}, {%8,%9}, {%0,%1,%2,%3};"
        : "+f"(d[0]), "+f"(d[1]), "+f"(d[2]), "+f"(d[3])
        : "r"(a[0]), "r"(a[1]), "r"(a[2]), "r"(a[3]), "r"(b[0]), "r"(b[1]));
}

// ---------------------------------------------------------------------------
// split fp32 -> (bf16 hi, bf16 lo).  DST: 0=X, 1=Wq, 2=Wp, 3=O
// ---------------------------------------------------------------------------
template<int DST>
__global__ __launch_bounds__(256) void split_kernel(const float* __restrict__ src,
                                                    size_t off4, int n4)
{
    __nv_bfloat16* hi = (DST==0) ? g_Xh : (DST==1) ? g_Wqh : (DST==2) ? g_Wph : g_Oh;
    __nv_bfloat16* lo = (DST==0) ? g_Xl : (DST==1) ? g_Wql : (DST==2) ? g_Wpl : g_Ol;
    const float* __restrict__ s = (DST==3) ? (const float*)g_O : src;

    int i = blockIdx.x * 256 + threadIdx.x;
    if (i >= n4) return;
    float4 v = ((const float4*)s)[i];
    __nv_bfloat16 h0 = __float2bfloat16(v.x);
    __nv_bfloat16 h1 = __float2bfloat16(v.y);
    __nv_bfloat16 h2 = __float2bfloat16(v.z);
    __nv_bfloat16 h3 = __float2bfloat16(v.w);
    __nv_bfloat16 l0 = __float2bfloat16(v.x - __bfloat162float(h0));
    __nv_bfloat16 l1 = __float2bfloat16(v.y - __bfloat162float(h1));
    __nv_bfloat16 l2 = __float2bfloat16(v.z - __bfloat162float(h2));
    __nv_bfloat16 l3 = __float2bfloat16(v.w - __bfloat162float(h3));
    size_t o = off4 + (size_t)i;
    ((__nv_bfloat162*)hi)[o*2 + 0] = __halves2bfloat162(h0, h1);
    ((__nv_bfloat162*)hi)[o*2 + 1] = __halves2bfloat162(h2, h3);
    ((__nv_bfloat162*)lo)[o*2 + 0] = __halves2bfloat162(l0, l1);
    ((__nv_bfloat162*)lo)[o*2 + 1] = __halves2bfloat162(l2, l3);
}

// ---------------------------------------------------------------------------
// mma.sync bf16x3 GEMM: D[128][128] tile of A @ B^T (+bias)
// A: [rows][768] (hi/lo), B(=W): [Nout][768] (hi/lo), both K-contiguous.
// MODE 0: qkv (Nout=2304), scatter into g_Q/g_K/g_V.  MODE 1: proj -> out.
// 256 threads, 8 warps: warp = (wm in 0..1) x (wn in 0..3) -> 64x32 per warp.
// smem: 1024 pad + 4x16KB tiles (loop) reused as Osm[128][132] (epilogue).
// ---------------------------------------------------------------------------
template<int MODE>
__global__ __launch_bounds__(256) void tc_gemm(const float* __restrict__ bias,
                                               float* __restrict__ outp)
{
    extern __shared__ char sm[];
    const uint32_t sb = smem_u32(sm) + 1024;
    const int tid = threadIdx.x;
    const int lane = tid & 31, wid = tid >> 5;
    const int wm = wid & 1, wn = wid >> 1;
    const int stream = blockIdx.z;
    const int m0 = blockIdx.y * 128;
    const int c0 = blockIdx.x * 128;

    const __nv_bfloat16* __restrict__ Ah =
        (MODE==0 ? g_Xh : g_Oh) + (size_t)stream * BN * C_;
    const __nv_bfloat16* __restrict__ Al =
        (MODE==0 ? g_Xl : g_Ol) + (size_t)stream * BN * C_;
    const __nv_bfloat16* __restrict__ Bh = MODE==0 ? g_Wqh : g_Wph;
    const __nv_bfloat16* __restrict__ Bl = MODE==0 ? g_Wql : g_Wpl;

    float acc[4][4][4];
#pragma unroll
    for (int i = 0; i < 4; i++)
#pragma unroll
        for (int j = 0; j < 4; j++)
#pragma unroll
            for (int k = 0; k < 4; k++) acc[i][j][k] = 0.f;

    // per-thread ldmatrix smem byte offsets (pre-swizzle base parts)
    // A frag: row = wm*64 + mf*16 + (lane&15), colbyte = k16*32 + (lane>>4)*16
    // B frag: row = wn*32 + nf*8 + (lane&7),  colbyte = k16*32 + ((lane>>3)&1)*16
    const int a_r  = wm*64 + (lane & 15);
    const int a_cb = (lane >> 4) * 16;
    const int b_r  = wn*32 + (lane & 7);
    const int b_cb = ((lane >> 3) & 1) * 16;

    const int NCH = C_ / 64;   // 12 chunks of K=64
    for (int ch = 0; ch < NCH; ch++) {
        const int kc = ch * 64;
        __syncthreads();   // previous chunk's mma fragment loads done
#pragma unroll
        for (int it = 0; it < 4; it++) {
            int idx = tid + it * 256;          // 0..1023 16B-chunks of one 16KB tile
            int r = idx >> 3, u = idx & 7;
            uint32_t so = swz((uint32_t)(r * 128 + u * 16));
            uint4 vah = *(const uint4*)(Ah + (size_t)(m0 + r) * C_ + kc + u * 8);
            uint4 val = *(const uint4*)(Al + (size_t)(m0 + r) * C_ + kc + u * 8);
            uint4 vbh = *(const uint4*)(Bh + (size_t)(c0 + r) * C_ + kc + u * 8);
            uint4 vbl = *(const uint4*)(Bl + (size_t)(c0 + r) * C_ + kc + u * 8);
            *(uint4*)(sm + 1024 +     0 + so) = vah;
            *(uint4*)(sm + 1024 + 16384 + so) = val;
            *(uint4*)(sm + 1024 + 32768 + so) = vbh;
            *(uint4*)(sm + 1024 + 49152 + so) = vbl;
        }
        __syncthreads();

#pragma unroll
        for (int k16 = 0; k16 < 4; k16++) {
            uint32_t bh[4][2], bl[4][2];
#pragma unroll
            for (int nf = 0; nf < 4; nf++) {
                uint32_t bo = swz((uint32_t)((b_r + nf*8) * 128 + k16*32 + b_cb));
                ldsm_x2(bh[nf], sb + 32768 + bo);
                ldsm_x2(bl[nf], sb + 49152 + bo);
            }
#pragma unroll
            for (int mf = 0; mf < 4; mf++) {
                uint32_t ao = swz((uint32_t)((a_r + mf*16) * 128 + k16*32 + a_cb));
                uint32_t ah[4], al[4];
                ldsm_x4(ah, sb +     0 + ao);
                ldsm_x4(al, sb + 16384 + ao);
#pragma unroll
                for (int nf = 0; nf < 4; nf++) {
                    mma16816(acc[mf][nf], ah, bh[nf]);
                    mma16816(acc[mf][nf], ah, bl[nf]);
                    mma16816(acc[mf][nf], al, bh[nf]);
                }
            }
        }
    }
    __syncthreads();   // done reading tiles; reuse smem as Osm

    // ---- stage accumulators to smem for vectorized global writes ----
    float* Osm = (float*)(sm + 1024);      // [128][132]
#pragma unroll
    for (int mf = 0; mf < 4; mf++) {
#pragma unroll
        for (int nf = 0; nf < 4; nf++) {
            int row = wm*64 + mf*16 + (lane >> 2);
            int col = wn*32 + nf*8 + (lane & 3)*2;
            Osm[row       * 132 + col    ] = acc[mf][nf][0];
            Osm[row       * 132 + col + 1] = acc[mf][nf][1];
            Osm[(row + 8) * 132 + col    ] = acc[mf][nf][2];
            Osm[(row + 8) * 132 + col + 1] = acc[mf][nf][3];
        }
    }
    __syncthreads();

#pragma unroll
    for (int it = 0; it < 16; it++) {
        int idx = tid + it * 256;             // 0..4095
        int r = idx >> 5, j4 = idx & 31;
        float4 v = *(float4*)&Osm[r * 132 + j4 * 4];
        float4 bb = *(const float4*)&bias[c0 + j4 * 4];
        v.x += bb.x; v.y += bb.y; v.z += bb.z; v.w += bb.w;
        int m = m0 + r;
        if (MODE == 0) {
            int cg = c0 + j4 * 4;
            int s = cg / C_;
            int rem = cg - s * C_;
            int h = rem >> 6, d = rem & 63;
            float* buf = (s == 0) ? g_Q : (s == 1) ? g_K : g_V;
            int b = m >> 10, n = m & 1023;
            *(float4*)&buf[((size_t)(b * H_ + h) * N_ + n) * 128 + stream * 64 + d] = v;
        } else {
            float* Y = outp + (size_t)stream * BN * C_;
            *(float4*)&Y[(size_t)m * C_ + c0 + j4 * 4] = v;
        }
    }
}

// ---------------------------------------------------------------------------
// flash attention, head-dim 128 (dual stream concat), 64-row Q tiles (fp32)
// ---------------------------------------------------------------------------
__global__ __launch_bounds__(256) void attn_kernel()
{
    extern __shared__ float smf[];
    float* Qt  = smf;                 // [128][68]
    float* Kt  = Qt + 128*68;         // [128][68]
    float* Vs  = Kt + 128*68;         // [64][132]
    float* Ps  = Vs + 64*132;         // [64][68]
    float* m_s = Ps + 64*68;
    float* l_s = m_s + 64;
    float* f_s = l_s + 64;

    const int bh = blockIdx.y;
    const int qt = blockIdx.x;
    const int t  = threadIdx.x;
    const int ry = t >> 4;
    const int cx = t & 15;

    const float* __restrict__ Qg = g_Q + (size_t)bh * N_ * 128 + (size_t)qt * 64 * 128;
    const float* __restrict__ Kg = g_K + (size_t)bh * N_ * 128;
    const float* __restrict__ Vg = g_V + (size_t)bh * N_ * 128;

#pragma unroll
    for (int it = 0; it < 8; it++) {
        int idx = t + it*256;
        int r = idx >> 5, d4 = idx & 31;
        float4 v = *(const float4*)&Qg[r*128 + d4*4];
        Qt[(d4*4+0)*68 + r] = v.x * SCALE;
        Qt[(d4*4+1)*68 + r] = v.y * SCALE;
        Qt[(d4*4+2)*68 + r] = v.z * SCALE;
        Qt[(d4*4+3)*68 + r] = v.w * SCALE;
    }
    if (t < 64) { m_s[t] = -1e30f; l_s[t] = 0.f; }

    float o[32];
#pragma unroll
    for (int i = 0; i < 32; i++) o[i] = 0.f;

    for (int kt = 0; kt < 16; kt++) {
        __syncthreads();
#pragma unroll
        for (int it = 0; it < 8; it++) {
            int idx = t + it*256;
            int r = idx >> 5, d4 = idx & 31;
            float4 kv = *(const float4*)&Kg[(kt*64 + r)*128 + d4*4];
            Kt[(d4*4+0)*68 + r] = kv.x;
            Kt[(d4*4+1)*68 + r] = kv.y;
            Kt[(d4*4+2)*68 + r] = kv.z;
            Kt[(d4*4+3)*68 + r] = kv.w;
            float4 vv = *(const float4*)&Vg[(kt*64 + r)*128 + d4*4];
            *(float4*)&Vs[r*132 + d4*4] = vv;
        }
        __syncthreads();

        float s4[4][4];
#pragma unroll
        for (int i = 0; i < 4; i++)
#pragma unroll
            for (int j = 0; j < 4; j++) s4[i][j] = 0.f;
#pragma unroll 4
        for (int k = 0; k < 128; k++) {
            float4 qv = *(const float4*)&Qt[k*68 + ry*4];
            float4 kv = *(const float4*)&Kt[k*68 + cx*4];
            s4[0][0] += qv.x*kv.x; s4[0][1] += qv.x*kv.y; s4[0][2] += qv.x*kv.z; s4[0][3] += qv.x*kv.w;
            s4[1][0] += qv.y*kv.x; s4[1][1] += qv.y*kv.y; s4[1][2] += qv.y*kv.z; s4[1][3] += qv.y*kv.w;
            s4[2][0] += qv.z*kv.x; s4[2][1] += qv.z*kv.y; s4[2][2] += qv.z*kv.z; s4[2][3] += qv.z*kv.w;
            s4[3][0] += qv.w*kv.x; s4[3][1] += qv.w*kv.y; s4[3][2] += qv.w*kv.z; s4[3][3] += qv.w*kv.w;
        }
#pragma unroll
        for (int i = 0; i < 4; i++)
            *(float4*)&Ps[(ry*4+i)*68 + cx*4] =
                make_float4(s4[i][0], s4[i][1], s4[i][2], s4[i][3]);
        __syncthreads();

        if (t < 64) {
            float mold = m_s[t];
            float mloc = mold;
            float* prow = &Ps[t*68];
#pragma unroll 8
            for (int c = 0; c < 64; c++) mloc = fmaxf(mloc, prow[c]);
            float sum = 0.f;
#pragma unroll 8
            for (int c = 0; c < 64; c++) {
                float p = __expf(prow[c] - mloc);
                prow[c] = p;
                sum += p;
            }
            float fac = __expf(mold - mloc);
            l_s[t] = l_s[t]*fac + sum;
            m_s[t] = mloc;
            f_s[t] = fac;
        }
        __syncthreads();

        float f0 = f_s[ry*4+0], f1 = f_s[ry*4+1], f2 = f_s[ry*4+2], f3 = f_s[ry*4+3];
#pragma unroll
        for (int j = 0; j < 8; j++) {
            o[0*8+j] *= f0; o[1*8+j] *= f1; o[2*8+j] *= f2; o[3*8+j] *= f3;
        }
#pragma unroll 2
        for (int j = 0; j < 64; j++) {
            float p0 = Ps[(ry*4+0)*68 + j];
            float p1 = Ps[(ry*4+1)*68 + j];
            float p2 = Ps[(ry*4+2)*68 + j];
            float p3 = Ps[(ry*4+3)*68 + j];
            float4 va = *(const float4*)&Vs[j*132 + cx*4];
            float4 vb = *(const float4*)&Vs[j*132 + 64 + cx*4];
            o[0]  += p0*va.x; o[1]  += p0*va.y; o[2]  += p0*va.z; o[3]  += p0*va.w;
            o[4]  += p0*vb.x; o[5]  += p0*vb.y; o[6]  += p0*vb.z; o[7]  += p0*vb.w;
            o[8]  += p1*va.x; o[9]  += p1*va.y; o[10] += p1*va.z; o[11] += p1*va.w;
            o[12] += p1*vb.x; o[13] += p1*vb.y; o[14] += p1*vb.z; o[15] += p1*vb.w;
            o[16] += p2*va.x; o[17] += p2*va.y; o[18] += p2*va.z; o[19] += p2*va.w;
            o[20] += p2*vb.x; o[21] += p2*vb.y; o[22] += p2*vb.z; o[23] += p2*vb.w;
            o[24] += p3*va.x; o[25] += p3*va.y; o[26] += p3*va.z; o[27] += p3*va.w;
            o[28] += p3*vb.x; o[29] += p3*vb.y; o[30] += p3*vb.z; o[31] += p3*vb.w;
        }
    }

    const int b = bh / H_, h = bh % H_;
    float* __restrict__ O1 = g_O;
    float* __restrict__ O2 = g_O + (size_t)BN * C_;
#pragma unroll
    for (int i = 0; i < 4; i++) {
        float linv = 1.f / l_s[ry*4+i];
        int n = qt*64 + ry*4 + i;
        size_t row = ((size_t)(b*N_ + n)) * C_ + h*64 + cx*4;
        float4 w1 = make_float4(o[i*8+0]*linv, o[i*8+1]*linv, o[i*8+2]*linv, o[i*8+3]*linv);
        float4 w2 = make_float4(o[i*8+4]*linv, o[i*8+5]*linv, o[i*8+6]*linv, o[i*8+7]*linv);
        *(float4*)&O1[row] = w1;
        *(float4*)&O2[row] = w2;
    }
}

// ---------------------------------------------------------------------------
extern "C" void kernel_launch(void* const* d_in, const int* in_sizes, int n_in,
                              void* d_out, int out_size)
{
    (void)in_sizes; (void)n_in; (void)out_size;
    const float* x1    = (const float*)d_in[0];
    const float* x2    = (const float*)d_in[1];
    const float* Wqkv  = (const float*)d_in[2];
    const float* bqkv  = (const float*)d_in[3];
    const float* Wproj = (const float*)d_in[4];
    const float* bproj = (const float*)d_in[5];
    float* out = (float*)d_out;

    const int nX4  = BN * C_ / 4;
    const int nWq4 = 3 * C_ * C_ / 4;
    const int nWp4 = C_ * C_ / 4;
    const int nO4  = 2 * BN * C_ / 4;

    split_kernel<0><<<(nX4 + 255) / 256, 256>>>(x1, 0, nX4);
    split_kernel<0><<<(nX4 + 255) / 256, 256>>>(x2, (size_t)nX4, nX4);
    split_kernel<1><<<(nWq4 + 255) / 256, 256>>>(Wqkv, 0, nWq4);
    split_kernel<2><<<(nWp4 + 255) / 256, 256>>>(Wproj, 0, nWp4);

    const int gemm_smem = 1024 + 128*132*4;   // 68608 B (tiles fit: 1024+65536)
    cudaFuncSetAttribute(tc_gemm<0>, cudaFuncAttributeMaxDynamicSharedMemorySize, gemm_smem);
    tc_gemm<0><<<dim3(18, 32, 2), 256, gemm_smem>>>(bqkv, nullptr);

    const int attn_smem = (128*68*2 + 64*132 + 64*68 + 192) * (int)sizeof(float);
    cudaFuncSetAttribute(attn_kernel, cudaFuncAttributeMaxDynamicSharedMemorySize, attn_smem);
    attn_kernel<<<dim3(16, 48), 256, attn_smem>>>();

    split_kernel<3><<<(nO4 + 255) / 256, 256>>>(nullptr, 0, nO4);

    cudaFuncSetAttribute(tc_gemm<1>, cudaFuncAttributeMaxDynamicSharedMemorySize, gemm_smem);
    tc_gemm<1><<<dim3(6, 32, 2), 256, gemm_smem>>>(bproj, out);
}

// round 4
// speedup vs baseline: 2.4312x; 1.8434x over previous
#include <cuda_runtime.h>
#include <cuda_bf16.h>
#include <cstdint>

#define B_ 4
#define N_ 1024
#define C_ 768
#define H_ 12
#define BN 4096
#define SCALE 0.125f

// ---------------- scratch (static device globals; no allocations) ----------
__device__ __align__(16) __nv_bfloat16 g_Qh[(size_t)B_*H_*N_*128];  // SCALE folded
__device__ __align__(16) __nv_bfloat16 g_Ql[(size_t)B_*H_*N_*128];
__device__ __align__(16) __nv_bfloat16 g_Kh[(size_t)B_*H_*N_*128];
__device__ __align__(16) __nv_bfloat16 g_Kl[(size_t)B_*H_*N_*128];
__device__ __align__(16) __nv_bfloat16 g_Vh[(size_t)B_*H_*N_*128];
__device__ __align__(16) __nv_bfloat16 g_Vl[(size_t)B_*H_*N_*128];

__device__ __align__(16) __nv_bfloat16 g_Xh[(size_t)2*BN*C_];
__device__ __align__(16) __nv_bfloat16 g_Xl[(size_t)2*BN*C_];
__device__ __align__(16) __nv_bfloat16 g_Wqh[(size_t)3*C_*C_];
__device__ __align__(16) __nv_bfloat16 g_Wql[(size_t)3*C_*C_];
__device__ __align__(16) __nv_bfloat16 g_Wph[(size_t)C_*C_];
__device__ __align__(16) __nv_bfloat16 g_Wpl[(size_t)C_*C_];
__device__ __align__(16) __nv_bfloat16 g_Oh[(size_t)2*BN*C_];
__device__ __align__(16) __nv_bfloat16 g_Ol[(size_t)2*BN*C_];

// ---------------- helpers ---------------------------------------------------
__device__ __forceinline__ uint32_t smem_u32(const void* p) {
    uint32_t a;
    asm("{ .reg .u64 t; cvta.to.shared.u64 t, %1; cvt.u32.u64 %0, t; }"
        : "=r"(a) : "l"(p));
    return a;
}
__device__ __forceinline__ uint32_t swz(uint32_t o) {   // SW128 within 128B rows
    return o ^ ((o >> 3) & 0x70);
}
__device__ __forceinline__ void ldsm_x4(uint32_t* r, uint32_t addr) {
    asm volatile("ldmatrix.sync.aligned.m8n8.x4.shared.b16 {%0,%1,%2,%3}, [%4];"
                 : "=r"(r[0]), "=r"(r[1]), "=r"(r[2]), "=r"(r[3]) : "r"(addr));
}
__device__ __forceinline__ void ldsm_x2(uint32_t* r, uint32_t addr) {
    asm volatile("ldmatrix.sync.aligned.m8n8.x2.shared.b16 {%0,%1}, [%2];"
                 : "=r"(r[0]), "=r"(r[1]) : "r"(addr));
}
__device__ __forceinline__ void ldsm_x2_t(uint32_t* r, uint32_t addr) {
    asm volatile("ldmatrix.sync.aligned.m8n8.x2.trans.shared.b16 {%0,%1}, [%2];"
                 : "=r"(r[0]), "=r"(r[1]) : "r"(addr));
}
__device__ __forceinline__ void mma16816(float* d, const uint32_t* a, const uint32_t* b) {
    asm volatile(
        "mma.sync.aligned.m16n8k16.row.col.f32.bf16.bf16.f32 "
        "{%0,%1,%2,%3}, {%4,%5,%6,%7}, {%8,%9}, {%0,%1,%2,%3};"
        : "+f"(d[0]), "+f"(d[1]), "+f"(d[2]), "+f"(d[3])
        : "r"(a[0]), "r"(a[1]), "r"(a[2]), "r"(a[3]), "r"(b[0]), "r"(b[1]));
}
__device__ __forceinline__ uint32_t pack_bf2(float a, float b) {
    __nv_bfloat162 t = __floats2bfloat162_rn(a, b);
    return *(uint32_t*)&t;
}

// ---------------------------------------------------------------------------
// split fp32 -> (bf16 hi, bf16 lo).  DST: 0=X, 1=Wq, 2=Wp
// ---------------------------------------------------------------------------
template<int DST>
__global__ __launch_bounds__(256) void split_kernel(const float* __restrict__ src,
                                                    size_t off4, int n4)
{
    __nv_bfloat16* hi = (DST==0) ? g_Xh : (DST==1) ? g_Wqh : g_Wph;
    __nv_bfloat16* lo = (DST==0) ? g_Xl : (DST==1) ? g_Wql : g_Wpl;

    int i = blockIdx.x * 256 + threadIdx.x;
    if (i >= n4) return;
    float4 v = ((const float4*)src)[i];
    __nv_bfloat16 h0 = __float2bfloat16(v.x);
    __nv_bfloat16 h1 = __float2bfloat16(v.y);
    __nv_bfloat16 h2 = __float2bfloat16(v.z);
    __nv_bfloat16 h3 = __float2bfloat16(v.w);
    __nv_bfloat16 l0 = __float2bfloat16(v.x - __bfloat162float(h0));
    __nv_bfloat16 l1 = __float2bfloat16(v.y - __bfloat162float(h1));
    __nv_bfloat16 l2 = __float2bfloat16(v.z - __bfloat162float(h2));
    __nv_bfloat16 l3 = __float2bfloat16(v.w - __bfloat162float(h3));
    size_t o = off4 + (size_t)i;
    ((__nv_bfloat162*)hi)[o*2 + 0] = __halves2bfloat162(h0, h1);
    ((__nv_bfloat162*)hi)[o*2 + 1] = __halves2bfloat162(h2, h3);
    ((__nv_bfloat162*)lo)[o*2 + 0] = __halves2bfloat162(l0, l1);
    ((__nv_bfloat162*)lo)[o*2 + 1] = __halves2bfloat162(l2, l3);
}

// ---------------------------------------------------------------------------
// mma.sync bf16x3 GEMM: 128x128 tile of A @ B^T (+bias)
// MODE 0: qkv -> Q/K/V bf16 hi/lo [B,H,N,128] (SCALE folded into Q)
// MODE 1: proj -> out (fp32)
// ---------------------------------------------------------------------------
template<int MODE>
__global__ __launch_bounds__(256) void tc_gemm(const float* __restrict__ bias,
                                               float* __restrict__ outp)
{
    extern __shared__ char sm[];
    const uint32_t sb = smem_u32(sm) + 1024;
    const int tid = threadIdx.x;
    const int lane = tid & 31, wid = tid >> 5;
    const int wm = wid & 1, wn = wid >> 1;
    const int stream = blockIdx.z;
    const int m0 = blockIdx.y * 128;
    const int c0 = blockIdx.x * 128;

    const __nv_bfloat16* __restrict__ Ah =
        (MODE==0 ? g_Xh : g_Oh) + (size_t)stream * BN * C_;
    const __nv_bfloat16* __restrict__ Al =
        (MODE==0 ? g_Xl : g_Ol) + (size_t)stream * BN * C_;
    const __nv_bfloat16* __restrict__ Bh = MODE==0 ? g_Wqh : g_Wph;
    const __nv_bfloat16* __restrict__ Bl = MODE==0 ? g_Wql : g_Wpl;

    float acc[4][4][4];
#pragma unroll
    for (int i = 0; i < 4; i++)
#pragma unroll
        for (int j = 0; j < 4; j++)
#pragma unroll
            for (int k = 0; k < 4; k++) acc[i][j][k] = 0.f;

    const int a_r  = wm*64 + (lane & 15);
    const int a_cb = (lane >> 4) * 16;
    const int b_r  = wn*32 + (lane & 7);
    const int b_cb = ((lane >> 3) & 1) * 16;

    const int NCH = C_ / 64;
    for (int ch = 0; ch < NCH; ch++) {
        const int kc = ch * 64;
        __syncthreads();
#pragma unroll
        for (int it = 0; it < 4; it++) {
            int idx = tid + it * 256;
            int r = idx >> 3, u = idx & 7;
            uint32_t so = swz((uint32_t)(r * 128 + u * 16));
            uint4 vah = *(const uint4*)(Ah + (size_t)(m0 + r) * C_ + kc + u * 8);
            uint4 val = *(const uint4*)(Al + (size_t)(m0 + r) * C_ + kc + u * 8);
            uint4 vbh = *(const uint4*)(Bh + (size_t)(c0 + r) * C_ + kc + u * 8);
            uint4 vbl = *(const uint4*)(Bl + (size_t)(c0 + r) * C_ + kc + u * 8);
            *(uint4*)(sm + 1024 +     0 + so) = vah;
            *(uint4*)(sm + 1024 + 16384 + so) = val;
            *(uint4*)(sm + 1024 + 32768 + so) = vbh;
            *(uint4*)(sm + 1024 + 49152 + so) = vbl;
        }
        __syncthreads();

#pragma unroll
        for (int k16 = 0; k16 < 4; k16++) {
            uint32_t bh[4][2], bl[4][2];
#pragma unroll
            for (int nf = 0; nf < 4; nf++) {
                uint32_t bo = swz((uint32_t)((b_r + nf*8) * 128 + k16*32 + b_cb));
                ldsm_x2(bh[nf], sb + 32768 + bo);
                ldsm_x2(bl[nf], sb + 49152 + bo);
            }
#pragma unroll
            for (int mf = 0; mf < 4; mf++) {
                uint32_t ao = swz((uint32_t)((a_r + mf*16) * 128 + k16*32 + a_cb));
                uint32_t ah[4], al[4];
                ldsm_x4(ah, sb +     0 + ao);
                ldsm_x4(al, sb + 16384 + ao);
#pragma unroll
                for (int nf = 0; nf < 4; nf++) {
                    mma16816(acc[mf][nf], ah, bh[nf]);
                    mma16816(acc[mf][nf], ah, bl[nf]);
                    mma16816(acc[mf][nf], al, bh[nf]);
                }
            }
        }
    }
    __syncthreads();

    float* Osm = (float*)(sm + 1024);      // [128][132]
#pragma unroll
    for (int mf = 0; mf < 4; mf++) {
#pragma unroll
        for (int nf = 0; nf < 4; nf++) {
            int row = wm*64 + mf*16 + (lane >> 2);
            int col = wn*32 + nf*8 + (lane & 3)*2;
            Osm[row       * 132 + col    ] = acc[mf][nf][0];
            Osm[row       * 132 + col + 1] = acc[mf][nf][1];
            Osm[(row + 8) * 132 + col    ] = acc[mf][nf][2];
            Osm[(row + 8) * 132 + col + 1] = acc[mf][nf][3];
        }
    }
    __syncthreads();

#pragma unroll
    for (int it = 0; it < 16; it++) {
        int idx = tid + it * 256;
        int r = idx >> 5, j4 = idx & 31;
        float4 v = *(float4*)&Osm[r * 132 + j4 * 4];
        float4 bb = *(const float4*)&bias[c0 + j4 * 4];
        v.x += bb.x; v.y += bb.y; v.z += bb.z; v.w += bb.w;
        int m = m0 + r;
        if (MODE == 0) {
            int cg = c0 + j4 * 4;
            int s = cg / C_;
            int rem = cg - s * C_;
            int h = rem >> 6, d = rem & 63;
            if (s == 0) { v.x *= SCALE; v.y *= SCALE; v.z *= SCALE; v.w *= SCALE; }
            __nv_bfloat16 h0 = __float2bfloat16(v.x);
            __nv_bfloat16 h1 = __float2bfloat16(v.y);
            __nv_bfloat16 h2 = __float2bfloat16(v.z);
            __nv_bfloat16 h3 = __float2bfloat16(v.w);
            uint2 hv, lv;
            hv.x = pack_bf2(v.x, v.y); hv.y = pack_bf2(v.z, v.w);
            lv.x = pack_bf2(v.x - __bfloat162float(h0), v.y - __bfloat162float(h1));
            lv.y = pack_bf2(v.z - __bfloat162float(h2), v.w - __bfloat162float(h3));
            __nv_bfloat16* bufh = (s == 0) ? g_Qh : (s == 1) ? g_Kh : g_Vh;
            __nv_bfloat16* bufl = (s == 0) ? g_Ql : (s == 1) ? g_Kl : g_Vl;
            int b = m >> 10, n = m & 1023;
            size_t base = ((size_t)(b * H_ + h) * N_ + n) * 128 + stream * 64 + d;
            *(uint2*)&bufh[base] = hv;
            *(uint2*)&bufl[base] = lv;
        } else {
            float* Y = outp + (size_t)stream * BN * C_;
            *(float4*)&Y[(size_t)m * C_ + c0 + j4 * 4] = v;
        }
    }
}

// ---------------------------------------------------------------------------
// flash attention on HMMA, head-dim 128 (dual-stream concat), bf16x3 split.
// 256 threads = 8 warps: warp w -> wm=w&3 (16 q-rows), wh=w>>2
//   (QK: n-half wh*32; PV: d-half wh*64 = output stream wh).
// smem: KH/KL/VH/VL/QH/QL 16KB each (two SW128 planes of 64x128B),
//       PH/PL 8KB, stats 1792B  -> 116480 B.
// ---------------------------------------------------------------------------
#define KH_ 0u
#define KL_ 16384u
#define VH_ 32768u
#define VL_ 49152u
#define QH_ 65536u
#define QL_ 81920u
#define PH_ 98304u
#define PL_ 106496u
#define STAT_ 114688u

__global__ __launch_bounds__(256, 2) void attn_mma()
{
    extern __shared__ char sm[];
    const uint32_t sb = smem_u32(sm);
    float* pmf   = (float*)(sm + STAT_);        // [2][64] partial max
    float* psf   = pmf + 128;                   // [2][64] partial sum
    float* m_s   = pmf + 256;                   // [64]
    float* l_s   = pmf + 320;                   // [64]
    float* fac_s = pmf + 384;                   // [64]

    const int tid = threadIdx.x;
    const int lane = tid & 31, w = tid >> 5;
    const int wm = w & 3, wh = w >> 2;
    const int qt = blockIdx.x, bh = blockIdx.y;
    const int b = bh / H_, h = bh - b * H_;
    const size_t kvb = (size_t)bh * N_ * 128;
    const int r0 = wm * 16 + (lane >> 2);

    // ---- load Q tile (swizzled planes) ----
    {
        const __nv_bfloat16* qh_g = g_Qh + kvb + (size_t)qt * 64 * 128;
        const __nv_bfloat16* ql_g = g_Ql + kvb + (size_t)qt * 64 * 128;
#pragma unroll
        for (int it = 0; it < 4; it++) {
            int idx = tid + it * 256;
            int row = idx >> 4, ch = idx & 15;
            uint32_t dst = (uint32_t)(ch >> 3) * 8192 + swz((uint32_t)(row * 128 + (ch & 7) * 16));
            *(uint4*)(sm + QH_ + dst) = *(const uint4*)(qh_g + row * 128 + ch * 8);
            *(uint4*)(sm + QL_ + dst) = *(const uint4*)(ql_g + row * 128 + ch * 8);
        }
    }
    if (tid < 64) { m_s[tid] = -1e30f; l_s[tid] = 0.f; }

    float o[8][4];
#pragma unroll
    for (int i = 0; i < 8; i++)
#pragma unroll
        for (int j = 0; j < 4; j++) o[i][j] = 0.f;

    for (int kt = 0; kt < 16; kt++) {
        __syncthreads();   // prior PV reads of K/V/P done
        {
            const __nv_bfloat16* kh_g = g_Kh + kvb + (size_t)kt * 64 * 128;
            const __nv_bfloat16* kl_g = g_Kl + kvb + (size_t)kt * 64 * 128;
            const __nv_bfloat16* vh_g = g_Vh + kvb + (size_t)kt * 64 * 128;
            const __nv_bfloat16* vl_g = g_Vl + kvb + (size_t)kt * 64 * 128;
#pragma unroll
            for (int it = 0; it < 4; it++) {
                int idx = tid + it * 256;
                int row = idx >> 4, ch = idx & 15;
                int src = row * 128 + ch * 8;
                uint32_t dst = (uint32_t)(ch >> 3) * 8192 + swz((uint32_t)(row * 128 + (ch & 7) * 16));
                *(uint4*)(sm + KH_ + dst) = *(const uint4*)(kh_g + src);
                *(uint4*)(sm + KL_ + dst) = *(const uint4*)(kl_g + src);
                *(uint4*)(sm + VH_ + dst) = *(const uint4*)(vh_g + src);
                *(uint4*)(sm + VL_ + dst) = *(const uint4*)(vl_g + src);
            }
        }
        __syncthreads();

        // ---- S = Q K^T (64x64, k=128), bf16x3 ----
        float sacc[4][4];
#pragma unroll
        for (int i = 0; i < 4; i++)
#pragma unroll
            for (int j = 0; j < 4; j++) sacc[i][j] = 0.f;

#pragma unroll
        for (int k16 = 0; k16 < 8; k16++) {
            uint32_t pl = (uint32_t)(k16 >> 2) * 8192;
            uint32_t ao = pl + swz((uint32_t)((wm*16 + (lane & 15)) * 128 + (k16 & 3)*32 + (lane >> 4)*16));
            uint32_t ah[4], al[4];
            ldsm_x4(ah, sb + QH_ + ao);
            ldsm_x4(al, sb + QL_ + ao);
            uint32_t bcb = (uint32_t)((k16 & 3)*32 + ((lane >> 3) & 1)*16);
#pragma unroll
            for (int nf = 0; nf < 4; nf++) {
                uint32_t bo = pl + swz((uint32_t)((wh*32 + nf*8 + (lane & 7)) * 128) + bcb);
                uint32_t bh2[2], bl2[2];
                ldsm_x2(bh2, sb + KH_ + bo);
                ldsm_x2(bl2, sb + KL_ + bo);
                mma16816(sacc[nf], ah, bh2);
                mma16816(sacc[nf], ah, bl2);
                mma16816(sacc[nf], al, bh2);
            }
        }

        // ---- online softmax ----
        float pm0 = -1e30f, pm1 = -1e30f;
#pragma unroll
        for (int nf = 0; nf < 4; nf++) {
            pm0 = fmaxf(pm0, fmaxf(sacc[nf][0], sacc[nf][1]));
            pm1 = fmaxf(pm1, fmaxf(sacc[nf][2], sacc[nf][3]));
        }
        pm0 = fmaxf(pm0, __shfl_xor_sync(0xffffffffu, pm0, 1));
        pm0 = fmaxf(pm0, __shfl_xor_sync(0xffffffffu, pm0, 2));
        pm1 = fmaxf(pm1, __shfl_xor_sync(0xffffffffu, pm1, 1));
        pm1 = fmaxf(pm1, __shfl_xor_sync(0xffffffffu, pm1, 2));
        if ((lane & 3) == 0) {
            pmf[wh*64 + r0]     = pm0;
            pmf[wh*64 + r0 + 8] = pm1;
        }
        __syncthreads();
        if (tid < 64) {
            float mo = m_s[tid];
            float mn = fmaxf(mo, fmaxf(pmf[tid], pmf[64 + tid]));
            fac_s[tid] = __expf(mo - mn);
            m_s[tid] = mn;
        }
        __syncthreads();

        float mn0 = m_s[r0], mn1 = m_s[r0 + 8];
        float sum0 = 0.f, sum1 = 0.f;
        uint32_t cb2 = (uint32_t)(wh*64 + (lane & 3)*4);
#pragma unroll
        for (int nf = 0; nf < 4; nf++) {
            float p0 = __expf(sacc[nf][0] - mn0);
            float p1 = __expf(sacc[nf][1] - mn0);
            float p2 = __expf(sacc[nf][2] - mn1);
            float p3 = __expf(sacc[nf][3] - mn1);
            sum0 += p0 + p1; sum1 += p2 + p3;
            __nv_bfloat16 h0 = __float2bfloat16(p0);
            __nv_bfloat16 h1 = __float2bfloat16(p1);
            __nv_bfloat16 h2 = __float2bfloat16(p2);
            __nv_bfloat16 h3 = __float2bfloat16(p3);
            uint32_t c = cb2 + (uint32_t)nf*16;
            *(uint32_t*)(sm + PH_ + swz((uint32_t)(r0*128) + c))       = pack_bf2(p0, p1);
            *(uint32_t*)(sm + PL_ + swz((uint32_t)(r0*128) + c))       =
                pack_bf2(p0 - __bfloat162float(h0), p1 - __bfloat162float(h1));
            *(uint32_t*)(sm + PH_ + swz((uint32_t)((r0+8)*128) + c))   = pack_bf2(p2, p3);
            *(uint32_t*)(sm + PL_ + swz((uint32_t)((r0+8)*128) + c))   =
                pack_bf2(p2 - __bfloat162float(h2), p3 - __bfloat162float(h3));
        }
        sum0 += __shfl_xor_sync(0xffffffffu, sum0, 1);
        sum0 += __shfl_xor_sync(0xffffffffu, sum0, 2);
        sum1 += __shfl_xor_sync(0xffffffffu, sum1, 1);
        sum1 += __shfl_xor_sync(0xffffffffu, sum1, 2);
        if ((lane & 3) == 0) {
            psf[wh*64 + r0]     = sum0;
            psf[wh*64 + r0 + 8] = sum1;
        }
        __syncthreads();
        if (tid < 64) l_s[tid] = l_s[tid] * fac_s[tid] + psf[tid] + psf[64 + tid];

        // ---- O = O*fac + P V ----
        float f0 = fac_s[r0], f1 = fac_s[r0 + 8];
#pragma unroll
        for (int nf = 0; nf < 8; nf++) {
            o[nf][0] *= f0; o[nf][1] *= f0;
            o[nf][2] *= f1; o[nf][3] *= f1;
        }
#pragma unroll
        for (int k16p = 0; k16p < 4; k16p++) {
            uint32_t po = swz((uint32_t)((wm*16 + (lane & 15)) * 128 + k16p*32 + (lane >> 4)*16));
            uint32_t pah[4], pal[4];
            ldsm_x4(pah, sb + PH_ + po);
            ldsm_x4(pal, sb + PL_ + po);
            uint32_t vrow = (uint32_t)((k16p*16 + (lane & 15)) * 128);
#pragma unroll
            for (int nf = 0; nf < 8; nf++) {
                uint32_t vo = (uint32_t)wh * 8192 + swz(vrow + (uint32_t)nf*16);
                uint32_t vh2[2], vl2[2];
                ldsm_x2_t(vh2, sb + VH_ + vo);
                ldsm_x2_t(vl2, sb + VL_ + vo);
                mma16816(o[nf], pah, vh2);
                mma16816(o[nf], pah, vl2);
                mma16816(o[nf], pal, vh2);
            }
        }
    }

    // ---- epilogue: normalize, split to bf16 hi/lo, write O (stream = wh) ----
    __syncthreads();
    float li0 = 1.f / l_s[r0], li1 = 1.f / l_s[r0 + 8];
    size_t srow = (size_t)wh * BN * C_ + (size_t)(b * N_ + qt * 64) * C_ + h * 64;
#pragma unroll
    for (int nf = 0; nf < 8; nf++) {
        int hd = nf*8 + (lane & 3)*2;
        size_t i0 = srow + (size_t)r0 * C_ + hd;
        size_t i1 = srow + (size_t)(r0 + 8) * C_ + hd;
        float v0 = o[nf][0]*li0, v1 = o[nf][1]*li0;
        float v2 = o[nf][2]*li1, v3 = o[nf][3]*li1;
        __nv_bfloat16 h0 = __float2bfloat16(v0);
        __nv_bfloat16 h1 = __float2bfloat16(v1);
        __nv_bfloat16 h2 = __float2bfloat16(v2);
        __nv_bfloat16 h3 = __float2bfloat16(v3);
        *(uint32_t*)&g_Oh[i0] = pack_bf2(v0, v1);
        *(uint32_t*)&g_Ol[i0] = pack_bf2(v0 - __bfloat162float(h0), v1 - __bfloat162float(h1));
        *(uint32_t*)&g_Oh[i1] = pack_bf2(v2, v3);
        *(uint32_t*)&g_Ol[i1] = pack_bf2(v2 - __bfloat162float(h2), v3 - __bfloat162float(h3));
    }
}

// ---------------------------------------------------------------------------
extern "C" void kernel_launch(void* const* d_in, const int* in_sizes, int n_in,
                              void* d_out, int out_size)
{
    (void)in_sizes; (void)n_in; (void)out_size;
    const float* x1    = (const float*)d_in[0];
    const float* x2    = (const float*)d_in[1];
    const float* Wqkv  = (const float*)d_in[2];
    const float* bqkv  = (const float*)d_in[3];
    const float* Wproj = (const float*)d_in[4];
    const float* bproj = (const float*)d_in[5];
    float* out = (float*)d_out;

    const int nX4  = BN * C_ / 4;
    const int nWq4 = 3 * C_ * C_ / 4;
    const int nWp4 = C_ * C_ / 4;

    split_kernel<0><<<(nX4 + 255) / 256, 256>>>(x1, 0, nX4);
    split_kernel<0><<<(nX4 + 255) / 256, 256>>>(x2, (size_t)nX4, nX4);
    split_kernel<1><<<(nWq4 + 255) / 256, 256>>>(Wqkv, 0, nWq4);
    split_kernel<2><<<(nWp4 + 255) / 256, 256>>>(Wproj, 0, nWp4);

    const int gemm_smem = 1024 + 128*132*4;   // 68608
    cudaFuncSetAttribute(tc_gemm<0>, cudaFuncAttributeMaxDynamicSharedMemorySize, gemm_smem);
    tc_gemm<0><<<dim3(18, 32, 2), 256, gemm_smem>>>(bqkv, nullptr);

    const int attn_smem = 116480;
    cudaFuncSetAttribute(attn_mma, cudaFuncAttributeMaxDynamicSharedMemorySize, attn_smem);
    attn_mma<<<dim3(16, 48), 256, attn_smem>>>();

    cudaFuncSetAttribute(tc_gemm<1>, cudaFuncAttributeMaxDynamicSharedMemorySize, gemm_smem);
    tc_gemm<1><<<dim3(6, 32, 2), 256, gemm_smem>>>(bproj, out);
}

// round 5
// speedup vs baseline: 3.8921x; 1.6009x over previous
#include <cuda_runtime.h>
#include <cuda_bf16.h>
#include <cstdint>

#define B_ 4
#define N_ 1024
#define C_ 768
#define H_ 12
#define BN 4096
#define SCALE 0.125f

// ---------------- scratch (static device globals; no allocations) ----------
__device__ __align__(16) __nv_bfloat16 g_Qh[(size_t)B_*H_*N_*128];  // SCALE folded
__device__ __align__(16) __nv_bfloat16 g_Ql[(size_t)B_*H_*N_*128];
__device__ __align__(16) __nv_bfloat16 g_Kh[(size_t)B_*H_*N_*128];
__device__ __align__(16) __nv_bfloat16 g_Kl[(size_t)B_*H_*N_*128];
__device__ __align__(16) __nv_bfloat16 g_Vh[(size_t)B_*H_*N_*128];
__device__ __align__(16) __nv_bfloat16 g_Vl[(size_t)B_*H_*N_*128];

__device__ __align__(16) __nv_bfloat16 g_Xh[(size_t)2*BN*C_];
__device__ __align__(16) __nv_bfloat16 g_Xl[(size_t)2*BN*C_];
__device__ __align__(16) __nv_bfloat16 g_Wqh[(size_t)3*C_*C_];
__device__ __align__(16) __nv_bfloat16 g_Wql[(size_t)3*C_*C_];
__device__ __align__(16) __nv_bfloat16 g_Wph[(size_t)C_*C_];
__device__ __align__(16) __nv_bfloat16 g_Wpl[(size_t)C_*C_];
__device__ __align__(16) __nv_bfloat16 g_Oh[(size_t)2*BN*C_];
__device__ __align__(16) __nv_bfloat16 g_Ol[(size_t)2*BN*C_];

// ---------------- helpers ---------------------------------------------------
__device__ __forceinline__ uint32_t smem_u32(const void* p) {
    uint32_t a;
    asm("{ .reg .u64 t; cvta.to.shared.u64 t, %1; cvt.u32.u64 %0, t; }"
        : "=r"(a) : "l"(p));
    return a;
}
__device__ __forceinline__ uint32_t swz(uint32_t o) {   // SW128 within 128B rows
    return o ^ ((o >> 3) & 0x70);
}
__device__ __forceinline__ void cpa16(uint32_t dst, const void* src) {
    asm volatile("cp.async.cg.shared.global [%0], [%1], 16;" :: "r"(dst), "l"(src));
}
__device__ __forceinline__ void cpa_commit() {
    asm volatile("cp.async.commit_group;" ::: "memory");
}
template<int N>
__device__ __forceinline__ void cpa_wait() {
    asm volatile("cp.async.wait_group %0;" :: "n"(N) : "memory");
}
__device__ __forceinline__ void ldsm_x4(uint32_t* r, uint32_t addr) {
    asm volatile("ldmatrix.sync.aligned.m8n8.x4.shared.b16 {%0,%1,%2,%3}, [%4];"
                 : "=r"(r[0]), "=r"(r[1]), "=r"(r[2]), "=r"(r[3]) : "r"(addr));
}
__device__ __forceinline__ void ldsm_x2(uint32_t* r, uint32_t addr) {
    asm volatile("ldmatrix.sync.aligned.m8n8.x2.shared.b16 {%0,%1}, [%2];"
                 : "=r"(r[0]), "=r"(r[1]) : "r"(addr));
}
__device__ __forceinline__ void ldsm_x2_t(uint32_t* r, uint32_t addr) {
    asm volatile("ldmatrix.sync.aligned.m8n8.x2.trans.shared.b16 {%0,%1}, [%2];"
                 : "=r"(r[0]), "=r"(r[1]) : "r"(addr));
}
__device__ __forceinline__ void mma16816(float* d, const uint32_t* a, const uint32_t* b) {
    asm volatile(
        "mma.sync.aligned.m16n8k16.row.col.f32.bf16.bf16.f32 "
        "{%0,%1,%2,%3}, {%4,%5,%6,%7}, {%8,%9}, {%0,%1,%2,%3};"
        : "+f"(d[0]), "+f"(d[1]), "+f"(d[2]), "+f"(d[3])
        : "r"(a[0]), "r"(a[1]), "r"(a[2]), "r"(a[3]), "r"(b[0]), "r"(b[1]));
}
__device__ __forceinline__ uint32_t pack_bf2(float a, float b) {
    __nv_bfloat162 t = __floats2bfloat162_rn(a, b);
    return *(uint32_t*)&t;
}

// ---------------------------------------------------------------------------
// split fp32 -> (bf16 hi, bf16 lo).  DST: 0=X, 1=Wq, 2=Wp
// ---------------------------------------------------------------------------
template<int DST>
__global__ __launch_bounds__(256) void split_kernel(const float* __restrict__ src,
                                                    size_t off4, int n4)
{
    __nv_bfloat16* hi = (DST==0) ? g_Xh : (DST==1) ? g_Wqh : g_Wph;
    __nv_bfloat16* lo = (DST==0) ? g_Xl : (DST==1) ? g_Wql : g_Wpl;

    int i = blockIdx.x * 256 + threadIdx.x;
    if (i >= n4) return;
    float4 v = ((const float4*)src)[i];
    __nv_bfloat16 h0 = __float2bfloat16(v.x);
    __nv_bfloat16 h1 = __float2bfloat16(v.y);
    __nv_bfloat16 h2 = __float2bfloat16(v.z);
    __nv_bfloat16 h3 = __float2bfloat16(v.w);
    __nv_bfloat16 l0 = __float2bfloat16(v.x - __bfloat162float(h0));
    __nv_bfloat16 l1 = __float2bfloat16(v.y - __bfloat162float(h1));
    __nv_bfloat16 l2 = __float2bfloat16(v.z - __bfloat162float(h2));
    __nv_bfloat16 l3 = __float2bfloat16(v.w - __bfloat162float(h3));
    size_t o = off4 + (size_t)i;
    ((__nv_bfloat162*)hi)[o*2 + 0] = __halves2bfloat162(h0, h1);
    ((__nv_bfloat162*)hi)[o*2 + 1] = __halves2bfloat162(h2, h3);
    ((__nv_bfloat162*)lo)[o*2 + 0] = __halves2bfloat162(l0, l1);
    ((__nv_bfloat162*)lo)[o*2 + 1] = __halves2bfloat162(l2, l3);
}

// ---------------------------------------------------------------------------
// mma.sync bf16x3 GEMM: 128x128 tile of A @ B^T (+bias), cp.async 2-stage.
// MODE 0: qkv -> Q/K/V bf16 hi/lo [B,H,N,128] (SCALE folded into Q)
// MODE 1: proj -> out (fp32)
// smem: 1024 + 2 stages x 64KB = 132096 B
// ---------------------------------------------------------------------------
template<int MODE>
__device__ __forceinline__ void gemm_issue_chunk(
    char* sm, uint32_t sbase,
    const __nv_bfloat16* Ah, const __nv_bfloat16* Al,
    const __nv_bfloat16* Bh, const __nv_bfloat16* Bl,
    int m0, int c0, int kc, int tid)
{
#pragma unroll
    for (int it = 0; it < 4; it++) {
        int idx = tid + it * 256;
        int r = idx >> 3, u = idx & 7;
        uint32_t so = swz((uint32_t)(r * 128 + u * 16));
        cpa16(sbase +     0 + so, Ah + (size_t)(m0 + r) * C_ + kc + u * 8);
        cpa16(sbase + 16384 + so, Al + (size_t)(m0 + r) * C_ + kc + u * 8);
        cpa16(sbase + 32768 + so, Bh + (size_t)(c0 + r) * C_ + kc + u * 8);
        cpa16(sbase + 49152 + so, Bl + (size_t)(c0 + r) * C_ + kc + u * 8);
    }
    cpa_commit();
}

template<int MODE>
__global__ __launch_bounds__(256) void tc_gemm(const float* __restrict__ bias,
                                               float* __restrict__ outp)
{
    extern __shared__ char sm[];
    const uint32_t sb = smem_u32(sm) + 1024;
    const int tid = threadIdx.x;
    const int lane = tid & 31, wid = tid >> 5;
    const int wm = wid & 1, wn = wid >> 1;
    const int stream = blockIdx.z;
    const int m0 = blockIdx.y * 128;
    const int c0 = blockIdx.x * 128;

    const __nv_bfloat16* __restrict__ Ah =
        (MODE==0 ? g_Xh : g_Oh) + (size_t)stream * BN * C_;
    const __nv_bfloat16* __restrict__ Al =
        (MODE==0 ? g_Xl : g_Ol) + (size_t)stream * BN * C_;
    const __nv_bfloat16* __restrict__ Bh = MODE==0 ? g_Wqh : g_Wph;
    const __nv_bfloat16* __restrict__ Bl = MODE==0 ? g_Wql : g_Wpl;

    float acc[4][4][4];
#pragma unroll
    for (int i = 0; i < 4; i++)
#pragma unroll
        for (int j = 0; j < 4; j++)
#pragma unroll
            for (int k = 0; k < 4; k++) acc[i][j][k] = 0.f;

    const int a_r  = wm*64 + (lane & 15);
    const int a_cb = (lane >> 4) * 16;
    const int b_r  = wn*32 + (lane & 7);
    const int b_cb = ((lane >> 3) & 1) * 16;

    const int NCH = C_ / 64;   // 12
    gemm_issue_chunk<MODE>(sm, sb + 0, Ah, Al, Bh, Bl, m0, c0, 0, tid);

    for (int ch = 0; ch < NCH; ch++) {
        const uint32_t stb = (uint32_t)(ch & 1) * 65536u;
        cpa_wait<0>();
        __syncthreads();       // stage ready + all warps done with other stage
        if (ch + 1 < NCH)
            gemm_issue_chunk<MODE>(sm, sb + ((ch + 1) & 1) * 65536u,
                                   Ah, Al, Bh, Bl, m0, c0, (ch + 1) * 64, tid);

#pragma unroll
        for (int k16 = 0; k16 < 4; k16++) {
            uint32_t bh[4][2], bl[4][2];
#pragma unroll
            for (int nf = 0; nf < 4; nf++) {
                uint32_t bo = stb + 32768 + swz((uint32_t)((b_r + nf*8) * 128 + k16*32 + b_cb));
                ldsm_x2(bh[nf], sb + bo);
                ldsm_x2(bl[nf], sb + bo + 16384);
            }
#pragma unroll
            for (int mf = 0; mf < 4; mf++) {
                uint32_t ao = stb + swz((uint32_t)((a_r + mf*16) * 128 + k16*32 + a_cb));
                uint32_t ah[4], al[4];
                ldsm_x4(ah, sb + ao);
                ldsm_x4(al, sb + ao + 16384);
#pragma unroll
                for (int nf = 0; nf < 4; nf++) {
                    mma16816(acc[mf][nf], ah, bh[nf]);
                    mma16816(acc[mf][nf], ah, bl[nf]);
                    mma16816(acc[mf][nf], al, bh[nf]);
                }
            }
        }
    }
    __syncthreads();   // done reading stage0 region; reuse as Osm

    float* Osm = (float*)(sm + 1024);      // [128][132]
#pragma unroll
    for (int mf = 0; mf < 4; mf++) {
#pragma unroll
        for (int nf = 0; nf < 4; nf++) {
            int row = wm*64 + mf*16 + (lane >> 2);
            int col = wn*32 + nf*8 + (lane & 3)*2;
            Osm[row       * 132 + col    ] = acc[mf][nf][0];
            Osm[row       * 132 + col + 1] = acc[mf][nf][1];
            Osm[(row + 8) * 132 + col    ] = acc[mf][nf][2];
            Osm[(row + 8) * 132 + col + 1] = acc[mf][nf][3];
        }
    }
    __syncthreads();

#pragma unroll
    for (int it = 0; it < 16; it++) {
        int idx = tid + it * 256;
        int r = idx >> 5, j4 = idx & 31;
        float4 v = *(float4*)&Osm[r * 132 + j4 * 4];
        float4 bb = *(const float4*)&bias[c0 + j4 * 4];
        v.x += bb.x; v.y += bb.y; v.z += bb.z; v.w += bb.w;
        int m = m0 + r;
        if (MODE == 0) {
            int cg = c0 + j4 * 4;
            int s = cg / C_;
            int rem = cg - s * C_;
            int h = rem >> 6, d = rem & 63;
            if (s == 0) { v.x *= SCALE; v.y *= SCALE; v.z *= SCALE; v.w *= SCALE; }
            __nv_bfloat16 h0 = __float2bfloat16(v.x);
            __nv_bfloat16 h1 = __float2bfloat16(v.y);
            __nv_bfloat16 h2 = __float2bfloat16(v.z);
            __nv_bfloat16 h3 = __float2bfloat16(v.w);
            uint2 hv, lv;
            hv.x = pack_bf2(v.x, v.y); hv.y = pack_bf2(v.z, v.w);
            lv.x = pack_bf2(v.x - __bfloat162float(h0), v.y - __bfloat162float(h1));
            lv.y = pack_bf2(v.z - __bfloat162float(h2), v.w - __bfloat162float(h3));
            __nv_bfloat16* bufh = (s == 0) ? g_Qh : (s == 1) ? g_Kh : g_Vh;
            __nv_bfloat16* bufl = (s == 0) ? g_Ql : (s == 1) ? g_Kl : g_Vl;
            int b = m >> 10, n = m & 1023;
            size_t base = ((size_t)(b * H_ + h) * N_ + n) * 128 + stream * 64 + d;
            *(uint2*)&bufh[base] = hv;
            *(uint2*)&bufl[base] = lv;
        } else {
            float* Y = outp + (size_t)stream * BN * C_;
            *(float4*)&Y[(size_t)m * C_ + c0 + j4 * 4] = v;
        }
    }
}

// ---------------------------------------------------------------------------
// flash attention on HMMA, head-dim 128 (dual-stream concat), bf16x3 split,
// cp.async 2-stage K/V pipeline, register-resident m/l.
// 256 threads = 8 warps: wm=w&3 (16 q-rows), wh=w>>2 (col half / d half).
// smem: 2 x (KH,KL,VH,VL 16KB) + QH/QL 16KB + PH/PL 8KB + stats = 181248 B
// ---------------------------------------------------------------------------
#define STG_ 65536u
#define KH_ 0u
#define KL_ 16384u
#define VH_ 32768u
#define VL_ 49152u
#define QH_ 131072u
#define QL_ 147456u
#define PH_ 163840u
#define PL_ 172032u
#define STAT_ 180224u

__device__ __forceinline__ void attn_issue_kv(
    char* sm, uint32_t stb,
    const __nv_bfloat16* kh_g, const __nv_bfloat16* kl_g,
    const __nv_bfloat16* vh_g, const __nv_bfloat16* vl_g, int tid)
{
#pragma unroll
    for (int it = 0; it < 4; it++) {
        int idx = tid + it * 256;
        int row = idx >> 4, ch = idx & 15;
        int src = row * 128 + ch * 8;
        uint32_t dst = stb + (uint32_t)(ch >> 3) * 8192 + swz((uint32_t)(row * 128 + (ch & 7) * 16));
        uint32_t sb = smem_u32(sm);
        cpa16(sb + KH_ + dst, kh_g + src);
        cpa16(sb + KL_ + dst, kl_g + src);
        cpa16(sb + VH_ + dst, vh_g + src);
        cpa16(sb + VL_ + dst, vl_g + src);
    }
    cpa_commit();
}

__global__ __launch_bounds__(256, 1) void attn_mma()
{
    extern __shared__ char sm[];
    const uint32_t sb = smem_u32(sm);
    float* pmf = (float*)(sm + STAT_);          // [2][64]
    float* psf = pmf + 128;                     // [2][64]

    const int tid = threadIdx.x;
    const int lane = tid & 31, w = tid >> 5;
    const int wm = w & 3, wh = w >> 2;
    const int qt = blockIdx.x, bh = blockIdx.y;
    const int b = bh / H_, h = bh - b * H_;
    const size_t kvb = (size_t)bh * N_ * 128;
    const int r0 = wm * 16 + (lane >> 2);

    const __nv_bfloat16* kh_g = g_Kh + kvb;
    const __nv_bfloat16* kl_g = g_Kl + kvb;
    const __nv_bfloat16* vh_g = g_Vh + kvb;
    const __nv_bfloat16* vl_g = g_Vl + kvb;

    attn_issue_kv(sm, 0, kh_g, kl_g, vh_g, vl_g, tid);

    // ---- load Q tile (regular) ----
    {
        const __nv_bfloat16* qh_g = g_Qh + kvb + (size_t)qt * 64 * 128;
        const __nv_bfloat16* ql_g = g_Ql + kvb + (size_t)qt * 64 * 128;
#pragma unroll
        for (int it = 0; it < 4; it++) {
            int idx = tid + it * 256;
            int row = idx >> 4, ch = idx & 15;
            uint32_t dst = (uint32_t)(ch >> 3) * 8192 + swz((uint32_t)(row * 128 + (ch & 7) * 16));
            *(uint4*)(sm + QH_ + dst) = *(const uint4*)(qh_g + row * 128 + ch * 8);
            *(uint4*)(sm + QL_ + dst) = *(const uint4*)(ql_g + row * 128 + ch * 8);
        }
    }

    float m0r = -1e30f, m1r = -1e30f, l0r = 0.f, l1r = 0.f;
    float o[8][4];
#pragma unroll
    for (int i = 0; i < 8; i++)
#pragma unroll
        for (int j = 0; j < 4; j++) o[i][j] = 0.f;

    for (int kt = 0; kt < 16; kt++) {
        const uint32_t stb = (uint32_t)(kt & 1) * STG_;
        cpa_wait<0>();
        __syncthreads();   // K/V stage ready; all warps done with other stage + P
        if (kt < 15)
            attn_issue_kv(sm, (uint32_t)((kt + 1) & 1) * STG_,
                          kh_g + (size_t)(kt + 1) * 64 * 128,
                          kl_g + (size_t)(kt + 1) * 64 * 128,
                          vh_g + (size_t)(kt + 1) * 64 * 128,
                          vl_g + (size_t)(kt + 1) * 64 * 128, tid);

        // ---- S = Q K^T (64x64, k=128), bf16x3 ----
        float sacc[4][4];
#pragma unroll
        for (int i = 0; i < 4; i++)
#pragma unroll
            for (int j = 0; j < 4; j++) sacc[i][j] = 0.f;

#pragma unroll
        for (int k16 = 0; k16 < 8; k16++) {
            uint32_t pl = (uint32_t)(k16 >> 2) * 8192;
            uint32_t ao = pl + swz((uint32_t)((wm*16 + (lane & 15)) * 128 + (k16 & 3)*32 + (lane >> 4)*16));
            uint32_t ah[4], al[4];
            ldsm_x4(ah, sb + QH_ + ao);
            ldsm_x4(al, sb + QL_ + ao);
            uint32_t bcb = (uint32_t)((k16 & 3)*32 + ((lane >> 3) & 1)*16);
#pragma unroll
            for (int nf = 0; nf < 4; nf++) {
                uint32_t bo = stb + pl + swz((uint32_t)((wh*32 + nf*8 + (lane & 7)) * 128) + bcb);
                uint32_t bh2[2], bl2[2];
                ldsm_x2(bh2, sb + KH_ + bo);
                ldsm_x2(bl2, sb + KL_ + bo);
                mma16816(sacc[nf], ah, bh2);
                mma16816(sacc[nf], ah, bl2);
                mma16816(sacc[nf], al, bh2);
            }
        }

        // ---- online softmax (register m/l, 2 smem exchanges) ----
        float pm0 = -1e30f, pm1 = -1e30f;
#pragma unroll
        for (int nf = 0; nf < 4; nf++) {
            pm0 = fmaxf(pm0, fmaxf(sacc[nf][0], sacc[nf][1]));
            pm1 = fmaxf(pm1, fmaxf(sacc[nf][2], sacc[nf][3]));
        }
        pm0 = fmaxf(pm0, __shfl_xor_sync(0xffffffffu, pm0, 1));
        pm0 = fmaxf(pm0, __shfl_xor_sync(0xffffffffu, pm0, 2));
        pm1 = fmaxf(pm1, __shfl_xor_sync(0xffffffffu, pm1, 1));
        pm1 = fmaxf(pm1, __shfl_xor_sync(0xffffffffu, pm1, 2));
        if ((lane & 3) == 0) {
            pmf[wh*64 + r0]     = pm0;
            pmf[wh*64 + r0 + 8] = pm1;
        }
        __syncthreads();
        float mn0 = fmaxf(m0r, fmaxf(pmf[r0],     pmf[64 + r0]));
        float mn1 = fmaxf(m1r, fmaxf(pmf[r0 + 8], pmf[64 + r0 + 8]));
        float f0 = __expf(m0r - mn0);
        float f1 = __expf(m1r - mn1);
        m0r = mn0; m1r = mn1;

        float sum0 = 0.f, sum1 = 0.f;
        uint32_t cb2 = (uint32_t)(wh*64 + (lane & 3)*4);
#pragma unroll
        for (int nf = 0; nf < 4; nf++) {
            float p0 = __expf(sacc[nf][0] - mn0);
            float p1 = __expf(sacc[nf][1] - mn0);
            float p2 = __expf(sacc[nf][2] - mn1);
            float p3 = __expf(sacc[nf][3] - mn1);
            sum0 += p0 + p1; sum1 += p2 + p3;
            __nv_bfloat16 h0 = __float2bfloat16(p0);
            __nv_bfloat16 h1 = __float2bfloat16(p1);
            __nv_bfloat16 h2 = __float2bfloat16(p2);
            __nv_bfloat16 h3 = __float2bfloat16(p3);
            uint32_t c = cb2 + (uint32_t)nf*16;
            *(uint32_t*)(sm + PH_ + swz((uint32_t)(r0*128) + c))     = pack_bf2(p0, p1);
            *(uint32_t*)(sm + PL_ + swz((uint32_t)(r0*128) + c))     =
                pack_bf2(p0 - __bfloat162float(h0), p1 - __bfloat162float(h1));
            *(uint32_t*)(sm + PH_ + swz((uint32_t)((r0+8)*128) + c)) = pack_bf2(p2, p3);
            *(uint32_t*)(sm + PL_ + swz((uint32_t)((r0+8)*128) + c)) =
                pack_bf2(p2 - __bfloat162float(h2), p3 - __bfloat162float(h3));
        }
        sum0 += __shfl_xor_sync(0xffffffffu, sum0, 1);
        sum0 += __shfl_xor_sync(0xffffffffu, sum0, 2);
        sum1 += __shfl_xor_sync(0xffffffffu, sum1, 1);
        sum1 += __shfl_xor_sync(0xffffffffu, sum1, 2);
        if ((lane & 3) == 0) {
            psf[wh*64 + r0]     = sum0;
            psf[wh*64 + r0 + 8] = sum1;
        }
        __syncthreads();   // P + psf visible
        l0r = l0r * f0 + psf[r0]     + psf[64 + r0];
        l1r = l1r * f1 + psf[r0 + 8] + psf[64 + r0 + 8];

        // ---- O = O*fac + P V ----
#pragma unroll
        for (int nf = 0; nf < 8; nf++) {
            o[nf][0] *= f0; o[nf][1] *= f0;
            o[nf][2] *= f1; o[nf][3] *= f1;
        }
#pragma unroll
        for (int k16p = 0; k16p < 4; k16p++) {
            uint32_t po = swz((uint32_t)((wm*16 + (lane & 15)) * 128 + k16p*32 + (lane >> 4)*16));
            uint32_t pah[4], pal[4];
            ldsm_x4(pah, sb + PH_ + po);
            ldsm_x4(pal, sb + PL_ + po);
            uint32_t vrow = (uint32_t)((k16p*16 + (lane & 15)) * 128);
#pragma unroll
            for (int nf = 0; nf < 8; nf++) {
                uint32_t vo = stb + (uint32_t)wh * 8192 + swz(vrow + (uint32_t)nf*16);
                uint32_t vh2[2], vl2[2];
                ldsm_x2_t(vh2, sb + VH_ + vo);
                ldsm_x2_t(vl2, sb + VL_ + vo);
                mma16816(o[nf], pah, vh2);
                mma16816(o[nf], pah, vl2);
                mma16816(o[nf], pal, vh2);
            }
        }
    }

    // ---- epilogue: normalize, split to bf16 hi/lo, write O (stream = wh) ----
    float li0 = 1.f / l0r, li1 = 1.f / l1r;
    size_t srow = (size_t)wh * BN * C_ + (size_t)(b * N_ + qt * 64) * C_ + h * 64;
#pragma unroll
    for (int nf = 0; nf < 8; nf++) {
        int hd = nf*8 + (lane & 3)*2;
        size_t i0 = srow + (size_t)r0 * C_ + hd;
        size_t i1 = srow + (size_t)(r0 + 8) * C_ + hd;
        float v0 = o[nf][0]*li0, v1 = o[nf][1]*li0;
        float v2 = o[nf][2]*li1, v3 = o[nf][3]*li1;
        __nv_bfloat16 h0 = __float2bfloat16(v0);
        __nv_bfloat16 h1 = __float2bfloat16(v1);
        __nv_bfloat16 h2 = __float2bfloat16(v2);
        __nv_bfloat16 h3 = __float2bfloat16(v3);
        *(uint32_t*)&g_Oh[i0] = pack_bf2(v0, v1);
        *(uint32_t*)&g_Ol[i0] = pack_bf2(v0 - __bfloat162float(h0), v1 - __bfloat162float(h1));
        *(uint32_t*)&g_Oh[i1] = pack_bf2(v2, v3);
        *(uint32_t*)&g_Ol[i1] = pack_bf2(v2 - __bfloat162float(h2), v3 - __bfloat162float(h3));
    }
}

// ---------------------------------------------------------------------------
extern "C" void kernel_launch(void* const* d_in, const int* in_sizes, int n_in,
                              void* d_out, int out_size)
{
    (void)in_sizes; (void)n_in; (void)out_size;
    const float* x1    = (const float*)d_in[0];
    const float* x2    = (const float*)d_in[1];
    const float* Wqkv  = (const float*)d_in[2];
    const float* bqkv  = (const float*)d_in[3];
    const float* Wproj = (const float*)d_in[4];
    const float* bproj = (const float*)d_in[5];
    float* out = (float*)d_out;

    const int nX4  = BN * C_ / 4;
    const int nWq4 = 3 * C_ * C_ / 4;
    const int nWp4 = C_ * C_ / 4;

    split_kernel<0><<<(nX4 + 255) / 256, 256>>>(x1, 0, nX4);
    split_kernel<0><<<(nX4 + 255) / 256, 256>>>(x2, (size_t)nX4, nX4);
    split_kernel<1><<<(nWq4 + 255) / 256, 256>>>(Wqkv, 0, nWq4);
    split_kernel<2><<<(nWp4 + 255) / 256, 256>>>(Wproj, 0, nWp4);

    const int gemm_smem = 1024 + 2 * 65536;   // 132096
    cudaFuncSetAttribute(tc_gemm<0>, cudaFuncAttributeMaxDynamicSharedMemorySize, gemm_smem);
    tc_gemm<0><<<dim3(18, 32, 2), 256, gemm_smem>>>(bqkv, nullptr);

    const int attn_smem = 181248;
    cudaFuncSetAttribute(attn_mma, cudaFuncAttributeMaxDynamicSharedMemorySize, attn_smem);
    attn_mma<<<dim3(16, 48), 256, attn_smem>>>();

    cudaFuncSetAttribute(tc_gemm<1>, cudaFuncAttributeMaxDynamicSharedMemorySize, gemm_smem);
    tc_gemm<1><<<dim3(6, 32, 2), 256, gemm_smem>>>(bproj, out);
}